// round 16
// baseline (speedup 1.0000x reference)
#include <cuda_runtime.h>
#include <cuda_bf16.h>
#include <cuda_fp16.h>
#include <stdint.h>

#define BB 2
#define SS 2048
#define DM 768
#define HH 12
#define DH 64
#define NROWS (BB*SS)      // 4096
#define KE 2304            // 3*DM: bf16 3-term ext (Q/K projections)
#define KE2 1536           // 2*DM: fp16 2-term ext (V/O projections)
#define NH (BB*HH)         // 24

// ---------------- scratch ----------------
__device__ __nv_bfloat16 g_xe[(size_t)NROWS * KE];      // x bf16 split-ext [hi|lo|hi]
__device__ __half        g_xh[(size_t)NROWS * KE2];     // x fp16 split-ext [hi|lo]
__device__ __nv_bfloat16 g_we[2][(size_t)DM * KE];      // Wq,Wk^T bf16 ext [hi|hi|lo]
__device__ __half        g_wh[2][(size_t)DM * KE2];     // Wv,Wo^T fp16 ext [w|w]
__device__ __nv_bfloat16 g_qe[(size_t)NH * SS * 128];   // Q [hi|lo], scale*log2e folded
__device__ __nv_bfloat16 g_ke[(size_t)NH * SS * 128];   // K [hi|lo]
__device__ __half        g_v[(size_t)NH * SS * DH];     // V fp16 row-major [24][2048][64]
__device__ __half        g_ae[(size_t)NROWS * KE2];     // attn out fp16 split-ext [hi|lo]

// ---------------- helpers ----------------
__device__ __forceinline__ uint32_t smem_u32(const void* p) {
    uint32_t a;
    asm("{ .reg .u64 t; cvta.to.shared.u64 t, %1; cvt.u32.u64 %0, t; }" : "=r"(a) : "l"(p));
    return a;
}
static __device__ __forceinline__ unsigned short bfu(__nv_bfloat16 h) {
    return *reinterpret_cast<unsigned short*>(&h);
}
static __device__ __forceinline__ unsigned short hfu(__half h) {
    return *reinterpret_cast<unsigned short*>(&h);
}
static __device__ __forceinline__ uint32_t pack2(__nv_bfloat16 a, __nv_bfloat16 b) {
    return (uint32_t)bfu(a) | ((uint32_t)bfu(b) << 16);
}
static __device__ __forceinline__ uint32_t pack2h(__half a, __half b) {
    return (uint32_t)hfu(a) | ((uint32_t)hfu(b) << 16);
}
static __device__ __forceinline__ void split2(float v, __nv_bfloat16& hi, __nv_bfloat16& lo) {
    hi = __float2bfloat16(v);
    lo = __float2bfloat16(v - __bfloat162float(hi));
}
static __device__ __forceinline__ void split2h(float v, __half& hi, __half& lo) {
    hi = __float2half_rn(v);
    lo = __float2half_rn(v - __half2float(hi));
}
static __device__ __forceinline__ float ex2(float x) {
    float r;
    asm("ex2.approx.f32 %0, %1;" : "=f"(r) : "f"(x));
    return r;
}
static __device__ __forceinline__ uint32_t cvt2h(float vlo, float vhi) {
    uint32_t r;
    asm("cvt.rn.f16x2.f32 %0, %1, %2;" : "=r"(r) : "f"(vhi), "f"(vlo));
    return r;
}
static __device__ __forceinline__ uint32_t sseg(uint32_t row, uint32_t seg) {
    return (seg & ~7u) | ((seg ^ row) & 7u);
}
__device__ __forceinline__ void cpa16(uint32_t dst, const void* src) {
    asm volatile("cp.async.cg.shared.global [%0], [%1], 16;" :: "r"(dst), "l"(src));
}
#define CPA_COMMIT() asm volatile("cp.async.commit_group;" ::: "memory")
#define CPA_WAIT0()  asm volatile("cp.async.wait_group 0;" ::: "memory")
#define CPA_WAIT1()  asm volatile("cp.async.wait_group 1;" ::: "memory")

__device__ __forceinline__ void ldmx4(uint32_t& r0, uint32_t& r1, uint32_t& r2, uint32_t& r3, uint32_t addr) {
    asm volatile("ldmatrix.sync.aligned.m8n8.x4.shared.b16 {%0,%1,%2,%3}, [%4];"
                 : "=r"(r0), "=r"(r1), "=r"(r2), "=r"(r3) : "r"(addr));
}
__device__ __forceinline__ void ldmx4t(uint32_t& r0, uint32_t& r1, uint32_t& r2, uint32_t& r3, uint32_t addr) {
    asm volatile("ldmatrix.sync.aligned.m8n8.x4.trans.shared.b16 {%0,%1,%2,%3}, [%4];"
                 : "=r"(r0), "=r"(r1), "=r"(r2), "=r"(r3) : "r"(addr));
}
__device__ __forceinline__ void mma_bf16(float* c, uint32_t a0, uint32_t a1, uint32_t a2, uint32_t a3,
                                         uint32_t b0, uint32_t b1) {
    asm volatile(
        "mma.sync.aligned.m16n8k16.row.col.f32.bf16.bf16.f32 "
        "{%0,%1,%2,%3}, {%4,%5,%6,%7}, {%8,%9}, {%0,%1,%2,%3};"
        : "+f"(c[0]), "+f"(c[1]), "+f"(c[2]), "+f"(c[3])
        : "r"(a0), "r"(a1), "r"(a2), "r"(a3), "r"(b0), "r"(b1));
}
__device__ __forceinline__ void mma_f16(float* c, uint32_t a0, uint32_t a1, uint32_t a2, uint32_t a3,
                                        uint32_t b0, uint32_t b1) {
    asm volatile(
        "mma.sync.aligned.m16n8k16.row.col.f32.f16.f16.f32 "
        "{%0,%1,%2,%3}, {%4,%5,%6,%7}, {%8,%9}, {%0,%1,%2,%3};"
        : "+f"(c[0]), "+f"(c[1]), "+f"(c[2]), "+f"(c[3])
        : "r"(a0), "r"(a1), "r"(a2), "r"(a3), "r"(b0), "r"(b1));
}

// ---------------- merged prep kernel ----------------
// blocks [0, 12288): x split; blocks [12288, 14592): W split/transpose
#define NXB (NROWS * DM / 256)   // 12288
__global__ void __launch_bounds__(256)
prep_all(const float* __restrict__ x,
         const float* __restrict__ Wq, const float* __restrict__ Wk,
         const float* __restrict__ Wv, const float* __restrict__ Wo) {
    int bid = blockIdx.x;
    if (bid < NXB) {
        int i = bid * 256 + threadIdx.x;
        int r = i / DM, c = i % DM;
        float v = x[i];
        __nv_bfloat16 h, l;
        split2(v, h, l);
        __nv_bfloat16* d = g_xe + (size_t)r * KE;
        d[c] = h; d[DM + c] = l; d[2 * DM + c] = h;       // bf16 [hi | lo | hi]
        __half hh, hl;
        split2h(v, hh, hl);
        __half* d2 = g_xh + (size_t)r * KE2;
        d2[c] = hh; d2[DM + c] = hl;                      // fp16 [hi | lo]
        return;
    }
    __shared__ float t[32][33];
    int zz = bid - NXB;                // 0..2303
    int z = zz / 576;                  // weight index
    int r2 = zz % 576;
    int k0 = (r2 / 24) * 32, o0 = (r2 % 24) * 32;
    const float* W = (z == 0) ? Wq : (z == 1) ? Wk : (z == 2) ? Wv : Wo;
    int tx = threadIdx.x & 31, ty = threadIdx.x >> 5;
#pragma unroll
    for (int rr = 0; rr < 32; rr += 8)
        t[ty + rr][tx] = W[(size_t)(k0 + ty + rr) * DM + o0 + tx];
    __syncthreads();
#pragma unroll
    for (int rr = 0; rr < 32; rr += 8) {
        int o = o0 + ty + rr;
        int k = k0 + tx;
        float v = t[tx][ty + rr];
        if (z < 2) {
            __nv_bfloat16 h, l;
            split2(v, h, l);
            __nv_bfloat16* d = &g_we[z][(size_t)o * KE];
            d[k] = h; d[DM + k] = h; d[2 * DM + k] = l;   // [hi | hi | lo]
        } else {
            __half hv = __float2half_rn(v);
            __half* d = &g_wh[z - 2][(size_t)o * KE2];
            d[k] = hv; d[DM + k] = hv;                    // [w | w]
        }
    }
}

// ---------------- HMMA GEMM: 64x128 tile, 3-stage cp.async pipeline ----------------
// 128 threads, 4 warps (2m x 2n), warp tile 32x64. smem: A 3x8KB + B 3x16KB = 72KB.
template <bool F16, int KEXT>
__device__ __forceinline__ void hmma_gemm(const uint16_t* __restrict__ A,
                                          const uint16_t* __restrict__ Bm,
                                          const float* __restrict__ bias,
                                          float* __restrict__ outp, int z) {
    extern __shared__ __align__(16) uint8_t gsm[];
    const uint32_t sb = smem_u32(gsm);
    const uint32_t GA = 0u, GB = 24576u;     // A stages 3x8KB @0, B stages 3x16KB @24576
    const int tid = threadIdx.x, lane = tid & 31, wid = tid >> 5;
    const int wm = wid & 1, wn = wid >> 1;
    const int row0 = blockIdx.y * 64, col0 = blockIdx.x * 128;

    float acc[2][8][4];
#pragma unroll
    for (int i = 0; i < 2; i++)
#pragma unroll
        for (int j = 0; j < 8; j++)
#pragma unroll
            for (int k = 0; k < 4; k++) acc[i][j][k] = 0.f;

    auto load_stage = [&](int s, int buf) {
#pragma unroll
        for (int t = 0; t < 4; t++) {
            int j = tid + t * 128, r = j >> 3, seg = j & 7;
            cpa16(sb + GA + buf * 8192u + r * 128 + sseg(r, seg) * 16,
                  A + (size_t)(row0 + r) * KEXT + s * 64 + seg * 8);
        }
#pragma unroll
        for (int t = 0; t < 8; t++) {
            int j = tid + t * 128, r = j >> 3, seg = j & 7;
            cpa16(sb + GB + buf * 16384u + r * 128 + sseg(r, seg) * 16,
                  Bm + (size_t)(col0 + r) * KEXT + s * 64 + seg * 8);
        }
    };

    const int NS = KEXT / 64;   // 36 or 24
    load_stage(0, 0); CPA_COMMIT();
    load_stage(1, 1); CPA_COMMIT();

    int buf = 0;
    for (int s = 0; s < NS; s++) {
        CPA_WAIT1();            // stage s's group complete (s+1's may be in flight)
        __syncthreads();        // all warps done with buffer (s+2)%3 (used at stage s-1)
        int bnext = buf + 2; if (bnext >= 3) bnext -= 3;
        if (s + 2 < NS) load_stage(s + 2, bnext);
        CPA_COMMIT();           // always commit (possibly empty group) to keep count aligned
        const uint32_t ab = sb + GA + buf * 8192u;
        const uint32_t bb = sb + GB + buf * 16384u;
#pragma unroll
        for (int ik = 0; ik < 4; ik++) {
            uint32_t af[2][4];
#pragma unroll
            for (int im = 0; im < 2; im++) {
                int r = wm * 32 + im * 16 + (lane & 15);
                int seg = ik * 2 + (lane >> 4);
                ldmx4(af[im][0], af[im][1], af[im][2], af[im][3], ab + r * 128 + sseg(r, seg) * 16);
            }
            uint32_t bf[8][2];
#pragma unroll
            for (int in2 = 0; in2 < 4; in2++) {
                int r = wn * 64 + in2 * 16 + (lane & 15);
                int seg = ik * 2 + (lane >> 4);
                uint32_t r0, r1, r2, r3;
                ldmx4(r0, r1, r2, r3, bb + r * 128 + sseg(r, seg) * 16);
                bf[in2 * 2 + 0][0] = r0; bf[in2 * 2 + 0][1] = r2;
                bf[in2 * 2 + 1][0] = r1; bf[in2 * 2 + 1][1] = r3;
            }
#pragma unroll
            for (int im = 0; im < 2; im++)
#pragma unroll
                for (int jn = 0; jn < 8; jn++) {
                    if (F16)
                        mma_f16(acc[im][jn], af[im][0], af[im][1], af[im][2], af[im][3],
                                bf[jn][0], bf[jn][1]);
                    else
                        mma_bf16(acc[im][jn], af[im][0], af[im][1], af[im][2], af[im][3],
                                 bf[jn][0], bf[jn][1]);
                }
        }
        buf = (buf == 2) ? 0 : buf + 1;
    }

    const int rbase = row0 + wm * 32;
    const int cbase = col0 + wn * 64;
#pragma unroll
    for (int im = 0; im < 2; im++) {
#pragma unroll
        for (int jn = 0; jn < 8; jn++) {
            int cg = cbase + jn * 8 + (lane & 3) * 2;
            float b0 = bias[cg], b1 = bias[cg + 1];
#pragma unroll
            for (int half = 0; half < 2; half++) {
                int rg = rbase + im * 16 + (lane >> 2) + half * 8;
                float v0 = acc[im][jn][2 * half + 0] + b0;
                float v1 = acc[im][jn][2 * half + 1] + b1;
                if (z == 3) {
                    *(float2*)&outp[(size_t)rg * DM + cg] = make_float2(v0, v1);
                } else {
                    int b = rg >> 11, sr = rg & 2047;
                    int h = cg >> 6, d = cg & 63;
                    int bh = b * HH + h;
                    if (z == 0) {
                        // fold 1/sqrt(64) * log2(e) so softmax can use exp2
                        v0 *= 0.180336880086f; v1 *= 0.180336880086f;
                    }
                    if (z == 0 || z == 1) {
                        __nv_bfloat16 h0, l0, h1, l1;
                        split2(v0, h0, l0); split2(v1, h1, l1);
                        uint32_t hp = pack2(h0, h1), lp = pack2(l0, l1);
                        size_t base = ((size_t)bh * SS + sr) * 128;
                        if (z == 0) {
                            *(uint32_t*)&g_qe[base + d] = hp;
                            *(uint32_t*)&g_qe[base + 64 + d] = lp;
                        } else {
                            *(uint32_t*)&g_ke[base + d] = hp;
                            *(uint32_t*)&g_ke[base + 64 + d] = lp;
                        }
                    } else {
                        // V: single fp16, row-major [bh][s][d] (coalesced 4B stores)
                        size_t base = ((size_t)bh * SS + sr) * DH + d;
                        *(uint32_t*)&g_v[base] = pack2h(__float2half_rn(v0), __float2half_rn(v1));
                    }
                }
            }
        }
    }
}

// merged QKV projection: z=0 Q (bf16), z=1 K (bf16), z=2 V (fp16).
__global__ void __launch_bounds__(128, 3)
hmma_qkv(const float* __restrict__ bq, const float* __restrict__ bk, const float* __restrict__ bv) {
    int z = blockIdx.z;
    if (z < 2)
        hmma_gemm<false, KE>((const uint16_t*)g_xe, (const uint16_t*)&g_we[z][0],
                             (z == 0) ? bq : bk, nullptr, z);
    else
        hmma_gemm<true, KE2>((const uint16_t*)g_xh, (const uint16_t*)&g_wh[0][0], bv, nullptr, 2);
}
__global__ void __launch_bounds__(128, 3)
hmma_proj(const float* __restrict__ bo, float* __restrict__ outp) {
    hmma_gemm<true, KE2>((const uint16_t*)g_ae, (const uint16_t*)&g_wh[1][0], bo, outp, 3);
}

// ---------------- HMMA flash attention (unchanged from R15) ----------------
#define AK   0u        // 2 x 32768
#define AV   65536u    // 2 x 16384
#define ASZ  98304u

__global__ void __launch_bounds__(256, 2) attn_hmma() {
    extern __shared__ __align__(16) uint8_t sm[];
    const uint32_t sb = smem_u32(sm);
    const int tid = threadIdx.x, lane = tid & 31, w = tid >> 5;
    const int q0 = blockIdx.x * 128, bh = blockIdx.y;
    const __nv_bfloat16* Qg = g_qe + ((size_t)bh * SS + q0) * 128;
    const __nv_bfloat16* Kg = g_ke + (size_t)bh * SS * 128;
    const __half* Vg = g_v + (size_t)bh * SS * DH;

    uint32_t qreg[8][4];
    {
        const __nv_bfloat16* Q0 = Qg + (size_t)(w * 16 + (lane >> 2)) * 128;
        const __nv_bfloat16* Q1 = Q0 + 8 * 128;
#pragma unroll
        for (int ch = 0; ch < 8; ch++) {
            int col = ch * 16 + (lane & 3) * 2;
            qreg[ch][0] = *(const uint32_t*)(Q0 + col);
            qreg[ch][1] = *(const uint32_t*)(Q1 + col);
            qreg[ch][2] = *(const uint32_t*)(Q0 + col + 8);
            qreg[ch][3] = *(const uint32_t*)(Q1 + col + 8);
        }
    }

#pragma unroll
    for (int t = 0; t < 8; t++) {
        int j = tid + t * 256, r = j >> 4, seg = j & 15;
        cpa16(sb + AK + r * 256 + sseg(r, seg) * 16, Kg + (size_t)r * 128 + seg * 8);
    }
#pragma unroll
    for (int t = 0; t < 4; t++) {
        int j = tid + t * 256, r = j >> 3, seg = j & 7;
        cpa16(sb + AV + r * 128 + sseg(r, seg) * 16, Vg + (size_t)r * DH + seg * 8);
    }
    CPA_COMMIT();

    float oacc[8][4];
#pragma unroll
    for (int j = 0; j < 8; j++)
#pragma unroll
        for (int k = 0; k < 4; k++) oacc[j][k] = 0.f;
    float rs0 = 0.f, rs1 = 0.f;

    for (int kt = 0; kt < 16; kt++) {
        const int b = kt & 1;
        CPA_WAIT0();
        __syncthreads();
        if (kt + 1 < 16) {
            const __nv_bfloat16* Kt = Kg + (size_t)(kt + 1) * 128 * 128;
            const __half* Vt = Vg + (size_t)(kt + 1) * 128 * DH;
#pragma unroll
            for (int t = 0; t < 8; t++) {
                int j = tid + t * 256, r = j >> 4, seg = j & 15;
                cpa16(sb + AK + (b ^ 1) * 32768u + r * 256 + sseg(r, seg) * 16,
                      Kt + (size_t)r * 128 + seg * 8);
            }
#pragma unroll
            for (int t = 0; t < 4; t++) {
                int j = tid + t * 256, r = j >> 3, seg = j & 7;
                cpa16(sb + AV + (b ^ 1) * 16384u + r * 128 + sseg(r, seg) * 16,
                      Vt + (size_t)r * DH + seg * 8);
            }
            CPA_COMMIT();
        }
        const uint32_t kb = sb + AK + b * 32768u;
        const uint32_t vb = sb + AV + b * 16384u;

#pragma unroll
        for (int c = 0; c < 8; c++) {
            float sA0[4] = {0.f, 0.f, 0.f, 0.f}, sA1[4] = {0.f, 0.f, 0.f, 0.f};
            float sB0[4] = {0.f, 0.f, 0.f, 0.f}, sB1[4] = {0.f, 0.f, 0.f, 0.f};
            float sC0[4] = {0.f, 0.f, 0.f, 0.f}, sC1[4] = {0.f, 0.f, 0.f, 0.f};
            const int krow = c * 16 + (lane & 15);
            const uint32_t krbase = kb + krow * 256;
#pragma unroll
            for (int ik = 0; ik < 4; ik++) {
                uint32_t r0, r1, r2, r3;
                int seg = ik * 2 + (lane >> 4);
                ldmx4(r0, r1, r2, r3, krbase + sseg(krow, seg) * 16);
                mma_bf16(sA0, qreg[ik][0], qreg[ik][1], qreg[ik][2], qreg[ik][3], r0, r2);
                mma_bf16(sA1, qreg[ik][0], qreg[ik][1], qreg[ik][2], qreg[ik][3], r1, r3);
                mma_bf16(sB0, qreg[4 + ik][0], qreg[4 + ik][1], qreg[4 + ik][2], qreg[4 + ik][3], r0, r2);
                mma_bf16(sB1, qreg[4 + ik][0], qreg[4 + ik][1], qreg[4 + ik][2], qreg[4 + ik][3], r1, r3);
            }
#pragma unroll
            for (int ik = 0; ik < 4; ik++) {
                uint32_t r0, r1, r2, r3;
                int seg = 8 + ik * 2 + (lane >> 4);
                ldmx4(r0, r1, r2, r3, krbase + sseg(krow, seg) * 16);
                mma_bf16(sC0, qreg[ik][0], qreg[ik][1], qreg[ik][2], qreg[ik][3], r0, r2);
                mma_bf16(sC1, qreg[ik][0], qreg[ik][1], qreg[ik][2], qreg[ik][3], r1, r3);
            }

            float e00 = ex2(sA0[0] + sB0[0] + sC0[0]);
            float e01 = ex2(sA0[1] + sB0[1] + sC0[1]);
            float e02 = ex2(sA0[2] + sB0[2] + sC0[2]);
            float e03 = ex2(sA0[3] + sB0[3] + sC0[3]);
            float e10 = ex2(sA1[0] + sB1[0] + sC1[0]);
            float e11 = ex2(sA1[1] + sB1[1] + sC1[1]);
            float e12 = ex2(sA1[2] + sB1[2] + sC1[2]);
            float e13 = ex2(sA1[3] + sB1[3] + sC1[3]);
            rs0 += (e00 + e01) + (e10 + e11);
            rs1 += (e02 + e03) + (e12 + e13);
            uint32_t ph[4];
            ph[0] = cvt2h(e00, e01);
            ph[1] = cvt2h(e02, e03);
            ph[2] = cvt2h(e10, e11);
            ph[3] = cvt2h(e12, e13);

            const int vrow = c * 16 + (lane & 15);
            const uint32_t vrbase = vb + vrow * 128;
#pragma unroll
            for (int j2 = 0; j2 < 4; j2++) {
                uint32_t r0, r1, r2, r3;
                int seg = j2 * 2 + (lane >> 4);
                ldmx4t(r0, r1, r2, r3, vrbase + sseg(vrow, seg) * 16);
                mma_f16(oacc[2 * j2],     ph[0], ph[1], ph[2], ph[3], r0, r1);
                mma_f16(oacc[2 * j2 + 1], ph[0], ph[1], ph[2], ph[3], r2, r3);
            }
        }
    }

    rs0 += __shfl_xor_sync(0xffffffffu, rs0, 1);
    rs0 += __shfl_xor_sync(0xffffffffu, rs0, 2);
    rs1 += __shfl_xor_sync(0xffffffffu, rs1, 1);
    rs1 += __shfl_xor_sync(0xffffffffu, rs1, 2);
    const float inv0 = 1.f / rs0, inv1 = 1.f / rs1;

    const int bg = bh / HH, h = bh % HH;
    const int grow0 = bg * SS + q0 + w * 16 + (lane >> 2);
#pragma unroll
    for (int j = 0; j < 8; j++) {
        int d = j * 8 + (lane & 3) * 2;
        int cc = h * 64 + d;
        {
            float v0 = oacc[j][0] * inv0, v1 = oacc[j][1] * inv0;
            __half h0, l0, h1, l1;
            split2h(v0, h0, l0); split2h(v1, h1, l1);
            size_t base = (size_t)grow0 * KE2;
            *(uint32_t*)&g_ae[base + cc] = pack2h(h0, h1);
            *(uint32_t*)&g_ae[base + DM + cc] = pack2h(l0, l1);
        }
        {
            float v0 = oacc[j][2] * inv1, v1 = oacc[j][3] * inv1;
            __half h0, l0, h1, l1;
            split2h(v0, h0, l0); split2h(v1, h1, l1);
            size_t base = (size_t)(grow0 + 8) * KE2;
            *(uint32_t*)&g_ae[base + cc] = pack2h(h0, h1);
            *(uint32_t*)&g_ae[base + DM + cc] = pack2h(l0, l1);
        }
    }
}

// ---------------------------------------------------------------------------
extern "C" void kernel_launch(void* const* d_in, const int* in_sizes, int n_in,
                              void* d_out, int out_size) {
    const float* x  = (const float*)d_in[0];
    const float* Wq = (const float*)d_in[1];
    const float* bq = (const float*)d_in[2];
    const float* Wk = (const float*)d_in[3];
    const float* bk = (const float*)d_in[4];
    const float* Wv = (const float*)d_in[5];
    const float* bv = (const float*)d_in[6];
    const float* Wo = (const float*)d_in[7];
    const float* bo = (const float*)d_in[8];
    float* out = (float*)d_out;

    static int attr_done = 0;
    if (!attr_done) {
        cudaFuncSetAttribute(hmma_qkv,  cudaFuncAttributeMaxDynamicSharedMemorySize, 73728);
        cudaFuncSetAttribute(hmma_proj, cudaFuncAttributeMaxDynamicSharedMemorySize, 73728);
        cudaFuncSetAttribute(attn_hmma, cudaFuncAttributeMaxDynamicSharedMemorySize, (int)ASZ);
        attr_done = 1;
    }

    prep_all<<<NXB + 2304, 256>>>(x, Wq, Wk, Wv, Wo);
    hmma_qkv<<<dim3(DM / 128, NROWS / 64, 3), 128, 73728>>>(bq, bk, bv);
    attn_hmma<<<dim3(SS / 128, NH), 256, ASZ>>>();
    hmma_proj<<<dim3(DM / 128, NROWS / 64), 128, 73728>>>(bo, out);
}

// round 17
// speedup vs baseline: 1.0099x; 1.0099x over previous
#include <cuda_runtime.h>
#include <cuda_bf16.h>
#include <cuda_fp16.h>
#include <stdint.h>

#define BB 2
#define SS 2048
#define DM 768
#define HH 12
#define DH 64
#define NROWS (BB*SS)      // 4096
#define KE 2304            // 3*DM: bf16 3-term ext (Q/K projections)
#define KE2 1536           // 2*DM: fp16 2-term ext (V/O projections)
#define NH (BB*HH)         // 24

// ---------------- scratch ----------------
__device__ __nv_bfloat16 g_xe[(size_t)NROWS * KE];      // x bf16 split-ext [hi|lo|hi]
__device__ __half        g_xh[(size_t)NROWS * KE2];     // x fp16 split-ext [hi|lo]
__device__ __nv_bfloat16 g_we[2][(size_t)DM * KE];      // Wq,Wk^T bf16 ext [hi|hi|lo]
__device__ __half        g_wh[2][(size_t)DM * KE2];     // Wv,Wo^T fp16 ext [w|w]
__device__ __nv_bfloat16 g_qe[(size_t)NH * SS * 128];   // Q [hi|lo], scale*log2e folded
__device__ __nv_bfloat16 g_ke[(size_t)NH * SS * 128];   // K [hi|lo]
__device__ __half        g_v[(size_t)NH * SS * DH];     // V fp16 row-major [24][2048][64]
__device__ __half        g_ae[(size_t)NROWS * KE2];     // attn out fp16 split-ext [hi|lo]

// ---------------- helpers ----------------
__device__ __forceinline__ uint32_t smem_u32(const void* p) {
    uint32_t a;
    asm("{ .reg .u64 t; cvta.to.shared.u64 t, %1; cvt.u32.u64 %0, t; }" : "=r"(a) : "l"(p));
    return a;
}
static __device__ __forceinline__ unsigned short bfu(__nv_bfloat16 h) {
    return *reinterpret_cast<unsigned short*>(&h);
}
static __device__ __forceinline__ unsigned short hfu(__half h) {
    return *reinterpret_cast<unsigned short*>(&h);
}
static __device__ __forceinline__ uint32_t pack2(__nv_bfloat16 a, __nv_bfloat16 b) {
    return (uint32_t)bfu(a) | ((uint32_t)bfu(b) << 16);
}
static __device__ __forceinline__ uint32_t pack2h(__half a, __half b) {
    return (uint32_t)hfu(a) | ((uint32_t)hfu(b) << 16);
}
static __device__ __forceinline__ void split2(float v, __nv_bfloat16& hi, __nv_bfloat16& lo) {
    hi = __float2bfloat16(v);
    lo = __float2bfloat16(v - __bfloat162float(hi));
}
static __device__ __forceinline__ void split2h(float v, __half& hi, __half& lo) {
    hi = __float2half_rn(v);
    lo = __float2half_rn(v - __half2float(hi));
}
static __device__ __forceinline__ float ex2(float x) {
    float r;
    asm("ex2.approx.f32 %0, %1;" : "=f"(r) : "f"(x));
    return r;
}
static __device__ __forceinline__ uint32_t cvt2h(float vlo, float vhi) {
    uint32_t r;
    asm("cvt.rn.f16x2.f32 %0, %1, %2;" : "=r"(r) : "f"(vhi), "f"(vlo));
    return r;
}
static __device__ __forceinline__ uint32_t sseg(uint32_t row, uint32_t seg) {
    return (seg & ~7u) | ((seg ^ row) & 7u);
}
__device__ __forceinline__ void cpa16(uint32_t dst, const void* src) {
    asm volatile("cp.async.cg.shared.global [%0], [%1], 16;" :: "r"(dst), "l"(src));
}
#define CPA_COMMIT() asm volatile("cp.async.commit_group;" ::: "memory")
#define CPA_WAIT0()  asm volatile("cp.async.wait_group 0;" ::: "memory")
#define CPA_WAIT1()  asm volatile("cp.async.wait_group 1;" ::: "memory")

__device__ __forceinline__ void ldmx4(uint32_t& r0, uint32_t& r1, uint32_t& r2, uint32_t& r3, uint32_t addr) {
    asm volatile("ldmatrix.sync.aligned.m8n8.x4.shared.b16 {%0,%1,%2,%3}, [%4];"
                 : "=r"(r0), "=r"(r1), "=r"(r2), "=r"(r3) : "r"(addr));
}
__device__ __forceinline__ void ldmx4t(uint32_t& r0, uint32_t& r1, uint32_t& r2, uint32_t& r3, uint32_t addr) {
    asm volatile("ldmatrix.sync.aligned.m8n8.x4.trans.shared.b16 {%0,%1,%2,%3}, [%4];"
                 : "=r"(r0), "=r"(r1), "=r"(r2), "=r"(r3) : "r"(addr));
}
__device__ __forceinline__ void mma_bf16(float* c, uint32_t a0, uint32_t a1, uint32_t a2, uint32_t a3,
                                         uint32_t b0, uint32_t b1) {
    asm volatile(
        "mma.sync.aligned.m16n8k16.row.col.f32.bf16.bf16.f32 "
        "{%0,%1,%2,%3}, {%4,%5,%6,%7}, {%8,%9}, {%0,%1,%2,%3};"
        : "+f"(c[0]), "+f"(c[1]), "+f"(c[2]), "+f"(c[3])
        : "r"(a0), "r"(a1), "r"(a2), "r"(a3), "r"(b0), "r"(b1));
}
__device__ __forceinline__ void mma_f16(float* c, uint32_t a0, uint32_t a1, uint32_t a2, uint32_t a3,
                                        uint32_t b0, uint32_t b1) {
    asm volatile(
        "mma.sync.aligned.m16n8k16.row.col.f32.f16.f16.f32 "
        "{%0,%1,%2,%3}, {%4,%5,%6,%7}, {%8,%9}, {%0,%1,%2,%3};"
        : "+f"(c[0]), "+f"(c[1]), "+f"(c[2]), "+f"(c[3])
        : "r"(a0), "r"(a1), "r"(a2), "r"(a3), "r"(b0), "r"(b1));
}

// ---------------- merged prep kernel ----------------
#define NXB (NROWS * DM / 256)   // 12288
__global__ void __launch_bounds__(256)
prep_all(const float* __restrict__ x,
         const float* __restrict__ Wq, const float* __restrict__ Wk,
         const float* __restrict__ Wv, const float* __restrict__ Wo) {
    int bid = blockIdx.x;
    if (bid < NXB) {
        int i = bid * 256 + threadIdx.x;
        int r = i / DM, c = i % DM;
        float v = x[i];
        __nv_bfloat16 h, l;
        split2(v, h, l);
        __nv_bfloat16* d = g_xe + (size_t)r * KE;
        d[c] = h; d[DM + c] = l; d[2 * DM + c] = h;
        __half hh, hl;
        split2h(v, hh, hl);
        __half* d2 = g_xh + (size_t)r * KE2;
        d2[c] = hh; d2[DM + c] = hl;
        return;
    }
    __shared__ float t[32][33];
    int zz = bid - NXB;
    int z = zz / 576;
    int r2 = zz % 576;
    int k0 = (r2 / 24) * 32, o0 = (r2 % 24) * 32;
    const float* W = (z == 0) ? Wq : (z == 1) ? Wk : (z == 2) ? Wv : Wo;
    int tx = threadIdx.x & 31, ty = threadIdx.x >> 5;
#pragma unroll
    for (int rr = 0; rr < 32; rr += 8)
        t[ty + rr][tx] = W[(size_t)(k0 + ty + rr) * DM + o0 + tx];
    __syncthreads();
#pragma unroll
    for (int rr = 0; rr < 32; rr += 8) {
        int o = o0 + ty + rr;
        int k = k0 + tx;
        float v = t[tx][ty + rr];
        if (z < 2) {
            __nv_bfloat16 h, l;
            split2(v, h, l);
            __nv_bfloat16* d = &g_we[z][(size_t)o * KE];
            d[k] = h; d[DM + k] = h; d[2 * DM + k] = l;
        } else {
            __half hv = __float2half_rn(v);
            __half* d = &g_wh[z - 2][(size_t)o * KE2];
            d[k] = hv; d[DM + k] = hv;
        }
    }
}

// ---------------- HMMA GEMM: 64x128 tile, 3-stage cp.async pipeline ----------------
template <bool F16, int KEXT>
__device__ __forceinline__ void hmma_gemm(const uint16_t* __restrict__ A,
                                          const uint16_t* __restrict__ Bm,
                                          const float* __restrict__ bias,
                                          float* __restrict__ outp, int z) {
    extern __shared__ __align__(16) uint8_t gsm[];
    const uint32_t sb = smem_u32(gsm);
    const uint32_t GA = 0u, GB = 24576u;
    const int tid = threadIdx.x, lane = tid & 31, wid = tid >> 5;
    const int wm = wid & 1, wn = wid >> 1;
    const int row0 = blockIdx.y * 64, col0 = blockIdx.x * 128;

    float acc[2][8][4];
#pragma unroll
    for (int i = 0; i < 2; i++)
#pragma unroll
        for (int j = 0; j < 8; j++)
#pragma unroll
            for (int k = 0; k < 4; k++) acc[i][j][k] = 0.f;

    auto load_stage = [&](int s, int buf) {
#pragma unroll
        for (int t = 0; t < 4; t++) {
            int j = tid + t * 128, r = j >> 3, seg = j & 7;
            cpa16(sb + GA + buf * 8192u + r * 128 + sseg(r, seg) * 16,
                  A + (size_t)(row0 + r) * KEXT + s * 64 + seg * 8);
        }
#pragma unroll
        for (int t = 0; t < 8; t++) {
            int j = tid + t * 128, r = j >> 3, seg = j & 7;
            cpa16(sb + GB + buf * 16384u + r * 128 + sseg(r, seg) * 16,
                  Bm + (size_t)(col0 + r) * KEXT + s * 64 + seg * 8);
        }
    };

    const int NS = KEXT / 64;
    load_stage(0, 0); CPA_COMMIT();
    load_stage(1, 1); CPA_COMMIT();

    int buf = 0;
    for (int s = 0; s < NS; s++) {
        CPA_WAIT1();
        __syncthreads();
        int bnext = buf + 2; if (bnext >= 3) bnext -= 3;
        if (s + 2 < NS) load_stage(s + 2, bnext);
        CPA_COMMIT();
        const uint32_t ab = sb + GA + buf * 8192u;
        const uint32_t bb = sb + GB + buf * 16384u;
#pragma unroll
        for (int ik = 0; ik < 4; ik++) {
            uint32_t af[2][4];
#pragma unroll
            for (int im = 0; im < 2; im++) {
                int r = wm * 32 + im * 16 + (lane & 15);
                int seg = ik * 2 + (lane >> 4);
                ldmx4(af[im][0], af[im][1], af[im][2], af[im][3], ab + r * 128 + sseg(r, seg) * 16);
            }
            uint32_t bf[8][2];
#pragma unroll
            for (int in2 = 0; in2 < 4; in2++) {
                int r = wn * 64 + in2 * 16 + (lane & 15);
                int seg = ik * 2 + (lane >> 4);
                uint32_t r0, r1, r2, r3;
                ldmx4(r0, r1, r2, r3, bb + r * 128 + sseg(r, seg) * 16);
                bf[in2 * 2 + 0][0] = r0; bf[in2 * 2 + 0][1] = r2;
                bf[in2 * 2 + 1][0] = r1; bf[in2 * 2 + 1][1] = r3;
            }
#pragma unroll
            for (int im = 0; im < 2; im++)
#pragma unroll
                for (int jn = 0; jn < 8; jn++) {
                    if (F16)
                        mma_f16(acc[im][jn], af[im][0], af[im][1], af[im][2], af[im][3],
                                bf[jn][0], bf[jn][1]);
                    else
                        mma_bf16(acc[im][jn], af[im][0], af[im][1], af[im][2], af[im][3],
                                 bf[jn][0], bf[jn][1]);
                }
        }
        buf = (buf == 2) ? 0 : buf + 1;
    }

    const int rbase = row0 + wm * 32;
    const int cbase = col0 + wn * 64;
#pragma unroll
    for (int im = 0; im < 2; im++) {
#pragma unroll
        for (int jn = 0; jn < 8; jn++) {
            int cg = cbase + jn * 8 + (lane & 3) * 2;
            float b0 = bias[cg], b1 = bias[cg + 1];
#pragma unroll
            for (int half = 0; half < 2; half++) {
                int rg = rbase + im * 16 + (lane >> 2) + half * 8;
                float v0 = acc[im][jn][2 * half + 0] + b0;
                float v1 = acc[im][jn][2 * half + 1] + b1;
                if (z == 3) {
                    *(float2*)&outp[(size_t)rg * DM + cg] = make_float2(v0, v1);
                } else {
                    int b = rg >> 11, sr = rg & 2047;
                    int h = cg >> 6, d = cg & 63;
                    int bh = b * HH + h;
                    if (z == 0) {
                        v0 *= 0.180336880086f; v1 *= 0.180336880086f;
                    }
                    if (z == 0 || z == 1) {
                        __nv_bfloat16 h0, l0, h1, l1;
                        split2(v0, h0, l0); split2(v1, h1, l1);
                        uint32_t hp = pack2(h0, h1), lp = pack2(l0, l1);
                        size_t base = ((size_t)bh * SS + sr) * 128;
                        if (z == 0) {
                            *(uint32_t*)&g_qe[base + d] = hp;
                            *(uint32_t*)&g_qe[base + 64 + d] = lp;
                        } else {
                            *(uint32_t*)&g_ke[base + d] = hp;
                            *(uint32_t*)&g_ke[base + 64 + d] = lp;
                        }
                    } else {
                        size_t base = ((size_t)bh * SS + sr) * DH + d;
                        *(uint32_t*)&g_v[base] = pack2h(__float2half_rn(v0), __float2half_rn(v1));
                    }
                }
            }
        }
    }
}

__global__ void __launch_bounds__(128, 3)
hmma_qkv(const float* __restrict__ bq, const float* __restrict__ bk, const float* __restrict__ bv) {
    int z = blockIdx.z;
    if (z < 2)
        hmma_gemm<false, KE>((const uint16_t*)g_xe, (const uint16_t*)&g_we[z][0],
                             (z == 0) ? bq : bk, nullptr, z);
    else
        hmma_gemm<true, KE2>((const uint16_t*)g_xh, (const uint16_t*)&g_wh[0][0], bv, nullptr, 2);
}
__global__ void __launch_bounds__(128, 3)
hmma_proj(const float* __restrict__ bo, float* __restrict__ outp) {
    hmma_gemm<true, KE2>((const uint16_t*)g_ae, (const uint16_t*)&g_wh[1][0], bo, outp, 3);
}

// ---------------- HMMA flash attention v10: chunk-level software pipeline ----------------
// Per tile: S(0); for c=1..8: exp(c-1) -> S(c) issues -> O(c-1). Same arithmetic/order.
#define AK   0u        // 2 x 32768
#define AV   65536u    // 2 x 16384
#define ASZ  98304u

__global__ void __launch_bounds__(256, 2) attn_hmma() {
    extern __shared__ __align__(16) uint8_t sm[];
    const uint32_t sb = smem_u32(sm);
    const int tid = threadIdx.x, lane = tid & 31, w = tid >> 5;
    const int q0 = blockIdx.x * 128, bh = blockIdx.y;
    const __nv_bfloat16* Qg = g_qe + ((size_t)bh * SS + q0) * 128;
    const __nv_bfloat16* Kg = g_ke + (size_t)bh * SS * 128;
    const __half* Vg = g_v + (size_t)bh * SS * DH;

    uint32_t qreg[8][4];
    {
        const __nv_bfloat16* Q0 = Qg + (size_t)(w * 16 + (lane >> 2)) * 128;
        const __nv_bfloat16* Q1 = Q0 + 8 * 128;
#pragma unroll
        for (int ch = 0; ch < 8; ch++) {
            int col = ch * 16 + (lane & 3) * 2;
            qreg[ch][0] = *(const uint32_t*)(Q0 + col);
            qreg[ch][1] = *(const uint32_t*)(Q1 + col);
            qreg[ch][2] = *(const uint32_t*)(Q0 + col + 8);
            qreg[ch][3] = *(const uint32_t*)(Q1 + col + 8);
        }
    }

#pragma unroll
    for (int t = 0; t < 8; t++) {
        int j = tid + t * 256, r = j >> 4, seg = j & 15;
        cpa16(sb + AK + r * 256 + sseg(r, seg) * 16, Kg + (size_t)r * 128 + seg * 8);
    }
#pragma unroll
    for (int t = 0; t < 4; t++) {
        int j = tid + t * 256, r = j >> 3, seg = j & 7;
        cpa16(sb + AV + r * 128 + sseg(r, seg) * 16, Vg + (size_t)r * DH + seg * 8);
    }
    CPA_COMMIT();

    float oacc[8][4];
#pragma unroll
    for (int j = 0; j < 8; j++)
#pragma unroll
        for (int k = 0; k < 4; k++) oacc[j][k] = 0.f;
    float rs0 = 0.f, rs1 = 0.f;

    float sA0[4], sA1[4], sB0[4], sB1[4], sC0[4], sC1[4];

    for (int kt = 0; kt < 16; kt++) {
        const int b = kt & 1;
        CPA_WAIT0();
        __syncthreads();
        if (kt + 1 < 16) {
            const __nv_bfloat16* Kt = Kg + (size_t)(kt + 1) * 128 * 128;
            const __half* Vt = Vg + (size_t)(kt + 1) * 128 * DH;
#pragma unroll
            for (int t = 0; t < 8; t++) {
                int j = tid + t * 256, r = j >> 4, seg = j & 15;
                cpa16(sb + AK + (b ^ 1) * 32768u + r * 256 + sseg(r, seg) * 16,
                      Kt + (size_t)r * 128 + seg * 8);
            }
#pragma unroll
            for (int t = 0; t < 4; t++) {
                int j = tid + t * 256, r = j >> 3, seg = j & 7;
                cpa16(sb + AV + (b ^ 1) * 16384u + r * 128 + sseg(r, seg) * 16,
                      Vt + (size_t)r * DH + seg * 8);
            }
            CPA_COMMIT();
        }
        const uint32_t kb = sb + AK + b * 32768u;
        const uint32_t vb = sb + AV + b * 16384u;

        // S phase for chunk c (fills sA/sB/sC)
        auto s_phase = [&](int c) {
#pragma unroll
            for (int k = 0; k < 4; k++) {
                sA0[k] = 0.f; sA1[k] = 0.f; sB0[k] = 0.f;
                sB1[k] = 0.f; sC0[k] = 0.f; sC1[k] = 0.f;
            }
            const int krow = c * 16 + (lane & 15);
            const uint32_t krbase = kb + krow * 256;
#pragma unroll
            for (int ik = 0; ik < 4; ik++) {
                uint32_t r0, r1, r2, r3;
                int seg = ik * 2 + (lane >> 4);
                ldmx4(r0, r1, r2, r3, krbase + sseg(krow, seg) * 16);
                mma_bf16(sA0, qreg[ik][0], qreg[ik][1], qreg[ik][2], qreg[ik][3], r0, r2);
                mma_bf16(sA1, qreg[ik][0], qreg[ik][1], qreg[ik][2], qreg[ik][3], r1, r3);
                mma_bf16(sB0, qreg[4 + ik][0], qreg[4 + ik][1], qreg[4 + ik][2], qreg[4 + ik][3], r0, r2);
                mma_bf16(sB1, qreg[4 + ik][0], qreg[4 + ik][1], qreg[4 + ik][2], qreg[4 + ik][3], r1, r3);
            }
#pragma unroll
            for (int ik = 0; ik < 4; ik++) {
                uint32_t r0, r1, r2, r3;
                int seg = 8 + ik * 2 + (lane >> 4);
                ldmx4(r0, r1, r2, r3, krbase + sseg(krow, seg) * 16);
                mma_bf16(sC0, qreg[ik][0], qreg[ik][1], qreg[ik][2], qreg[ik][3], r0, r2);
                mma_bf16(sC1, qreg[ik][0], qreg[ik][1], qreg[ik][2], qreg[ik][3], r1, r3);
            }
        };

        s_phase(0);
#pragma unroll
        for (int c = 1; c <= 8; c++) {
            // exp for chunk c-1 (consumes S accs)
            float e00 = ex2(sA0[0] + sB0[0] + sC0[0]);
            float e01 = ex2(sA0[1] + sB0[1] + sC0[1]);
            float e02 = ex2(sA0[2] + sB0[2] + sC0[2]);
            float e03 = ex2(sA0[3] + sB0[3] + sC0[3]);
            float e10 = ex2(sA1[0] + sB1[0] + sC1[0]);
            float e11 = ex2(sA1[1] + sB1[1] + sC1[1]);
            float e12 = ex2(sA1[2] + sB1[2] + sC1[2]);
            float e13 = ex2(sA1[3] + sB1[3] + sC1[3]);
            rs0 += (e00 + e01) + (e10 + e11);
            rs1 += (e02 + e03) + (e12 + e13);
            uint32_t ph[4];
            ph[0] = cvt2h(e00, e01);
            ph[1] = cvt2h(e02, e03);
            ph[2] = cvt2h(e10, e11);
            ph[3] = cvt2h(e12, e13);

            // issue S for chunk c while exps/cvts retire
            if (c < 8) s_phase(c);

            // O for chunk c-1
            const int cp = c - 1;
            const int vrow = cp * 16 + (lane & 15);
            const uint32_t vrbase = vb + vrow * 128;
#pragma unroll
            for (int j2 = 0; j2 < 4; j2++) {
                uint32_t r0, r1, r2, r3;
                int seg = j2 * 2 + (lane >> 4);
                ldmx4t(r0, r1, r2, r3, vrbase + sseg(vrow, seg) * 16);
                mma_f16(oacc[2 * j2],     ph[0], ph[1], ph[2], ph[3], r0, r1);
                mma_f16(oacc[2 * j2 + 1], ph[0], ph[1], ph[2], ph[3], r2, r3);
            }
        }
    }

    rs0 += __shfl_xor_sync(0xffffffffu, rs0, 1);
    rs0 += __shfl_xor_sync(0xffffffffu, rs0, 2);
    rs1 += __shfl_xor_sync(0xffffffffu, rs1, 1);
    rs1 += __shfl_xor_sync(0xffffffffu, rs1, 2);
    const float inv0 = 1.f / rs0, inv1 = 1.f / rs1;

    const int bg = bh / HH, h = bh % HH;
    const int grow0 = bg * SS + q0 + w * 16 + (lane >> 2);
#pragma unroll
    for (int j = 0; j < 8; j++) {
        int d = j * 8 + (lane & 3) * 2;
        int cc = h * 64 + d;
        {
            float v0 = oacc[j][0] * inv0, v1 = oacc[j][1] * inv0;
            __half h0, l0, h1, l1;
            split2h(v0, h0, l0); split2h(v1, h1, l1);
            size_t base = (size_t)grow0 * KE2;
            *(uint32_t*)&g_ae[base + cc] = pack2h(h0, h1);
            *(uint32_t*)&g_ae[base + DM + cc] = pack2h(l0, l1);
        }
        {
            float v0 = oacc[j][2] * inv1, v1 = oacc[j][3] * inv1;
            __half h0, l0, h1, l1;
            split2h(v0, h0, l0); split2h(v1, h1, l1);
            size_t base = (size_t)(grow0 + 8) * KE2;
            *(uint32_t*)&g_ae[base + cc] = pack2h(h0, h1);
            *(uint32_t*)&g_ae[base + DM + cc] = pack2h(l0, l1);
        }
    }
}

// ---------------------------------------------------------------------------
extern "C" void kernel_launch(void* const* d_in, const int* in_sizes, int n_in,
                              void* d_out, int out_size) {
    const float* x  = (const float*)d_in[0];
    const float* Wq = (const float*)d_in[1];
    const float* bq = (const float*)d_in[2];
    const float* Wk = (const float*)d_in[3];
    const float* bk = (const float*)d_in[4];
    const float* Wv = (const float*)d_in[5];
    const float* bv = (const float*)d_in[6];
    const float* Wo = (const float*)d_in[7];
    const float* bo = (const float*)d_in[8];
    float* out = (float*)d_out;

    static int attr_done = 0;
    if (!attr_done) {
        cudaFuncSetAttribute(hmma_qkv,  cudaFuncAttributeMaxDynamicSharedMemorySize, 73728);
        cudaFuncSetAttribute(hmma_proj, cudaFuncAttributeMaxDynamicSharedMemorySize, 73728);
        cudaFuncSetAttribute(attn_hmma, cudaFuncAttributeMaxDynamicSharedMemorySize, (int)ASZ);
        attr_done = 1;
    }

    prep_all<<<NXB + 2304, 256>>>(x, Wq, Wk, Wv, Wo);
    hmma_qkv<<<dim3(DM / 128, NROWS / 64, 3), 128, 73728>>>(bq, bk, bv);
    attn_hmma<<<dim3(SS / 128, NH), 256, ASZ>>>();
    hmma_proj<<<dim3(DM / 128, NROWS / 64), 128, 73728>>>(bo, out);
}